// round 7
// baseline (speedup 1.0000x reference)
#include <cuda_runtime.h>
#include <math.h>

// MaxNormPooling2D: quaternion max-norm 2x2 pooling, stride 2, VALID.
// Inputs: x0..x3 each (B=16, H=128, W=128, C=64) fp32, NHWC.
// Output: concatenated (out0..out3), each (16, 64, 64, 64) fp32.
//
// R6: proven DRAM-ceiling-bound (~5.9 TB/s across 3 configs). This round
// removes the last structural overhead: persistent grid-stride launch at
// exactly (148 SMs x 3 resident blocks) so there is no partial final wave
// and no wave-transition gaps; all blocks drain simultaneously.
// Back to the float4-per-thread layout (best bench time, 66 regs -> 3
// blocks/SM resident).

#define B_  16
#define H_  128
#define W_  128
#define C_  64
#define HO_ 64
#define WO_ 64

#define C4_ 16
#define NWORK_TOTAL (B_ * HO_ * WO_ * C4_)      // 1,048,576 work items
#define OUT_COMP_F4 (B_ * HO_ * WO_ * C_ / 4)   // 1,048,576

#define THREADS_  256
#define NSM_      148
#define BLKS_PER_SM_ 3
#define GRID_     (NSM_ * BLKS_PER_SM_)          // 444 persistent blocks

__global__ __launch_bounds__(THREADS_, BLKS_PER_SM_) void maxnorm_pool_kernel(
    const float4* __restrict__ x0,
    const float4* __restrict__ x1,
    const float4* __restrict__ x2,
    const float4* __restrict__ x3,
    float4* __restrict__ out)
{
    const int stride = GRID_ * THREADS_;  // 113,664

    for (int t = blockIdx.x * THREADS_ + threadIdx.x; t < NWORK_TOTAL; t += stride) {
        int c4  = t & (C4_ - 1);
        int pix = t >> 4;             // b*HO*WO + ho*WO + wo
        int wo  = pix & (WO_ - 1);
        int ho  = (pix >> 6) & (HO_ - 1);
        int b   = pix >> 12;

        int h0 = ho << 1;
        int w0 = wo << 1;

        // input index in float4 units: ((b*H + h)*W + w)*C4 + c4
        // window positions in row-major order: (0,0),(0,1),(1,0),(1,1)
        int base = ((b * H_ + h0) * W_ + w0) * C4_ + c4;
        int off[4];
        off[0] = base;
        off[1] = base + C4_;          // dw=1
        off[2] = base + W_ * C4_;     // dh=1
        off[3] = base + W_ * C4_ + C4_;

        // best norm per lane (norms >= 0, so -1 guarantees p=0 wins first ->
        // first-max tie-break like TF/argmax)
        float4 bn = make_float4(-1.f, -1.f, -1.f, -1.f);
        float4 o0, o1, o2, o3;

#pragma unroll
        for (int p = 0; p < 4; ++p) {
            float4 a0 = x0[off[p]];
            float4 a1 = x1[off[p]];
            float4 a2 = x2[off[p]];
            float4 a3 = x3[off[p]];

            // sequential sum order x0^2 + x1^2 + x2^2 + x3^2, then sqrt —
            // matches the reference's comparison domain for tie behavior.
            float nx = sqrtf(a0.x * a0.x + a1.x * a1.x + a2.x * a2.x + a3.x * a3.x);
            float ny = sqrtf(a0.y * a0.y + a1.y * a1.y + a2.y * a2.y + a3.y * a3.y);
            float nz = sqrtf(a0.z * a0.z + a1.z * a1.z + a2.z * a2.z + a3.z * a3.z);
            float nw = sqrtf(a0.w * a0.w + a1.w * a1.w + a2.w * a2.w + a3.w * a3.w);

            if (nx > bn.x) { bn.x = nx; o0.x = a0.x; o1.x = a1.x; o2.x = a2.x; o3.x = a3.x; }
            if (ny > bn.y) { bn.y = ny; o0.y = a0.y; o1.y = a1.y; o2.y = a2.y; o3.y = a3.y; }
            if (nz > bn.z) { bn.z = nz; o0.z = a0.z; o1.z = a1.z; o2.z = a2.z; o3.z = a3.z; }
            if (nw > bn.w) { bn.w = nw; o0.w = a0.w; o1.w = a1.w; o2.w = a2.w; o3.w = a3.w; }
        }

        int obase = pix * C4_ + c4;   // within one component, float4 units
        out[obase]                   = o0;
        out[obase + OUT_COMP_F4]     = o1;
        out[obase + 2 * OUT_COMP_F4] = o2;
        out[obase + 3 * OUT_COMP_F4] = o3;
    }
}

extern "C" void kernel_launch(void* const* d_in, const int* in_sizes, int n_in,
                              void* d_out, int out_size)
{
    const float4* x0 = (const float4*)d_in[0];
    const float4* x1 = (const float4*)d_in[1];
    const float4* x2 = (const float4*)d_in[2];
    const float4* x3 = (const float4*)d_in[3];
    float4* out = (float4*)d_out;

    maxnorm_pool_kernel<<<GRID_, THREADS_>>>(x0, x1, x2, x3, out);
}

// round 8
// speedup vs baseline: 1.0006x; 1.0006x over previous
#include <cuda_runtime.h>
#include <math.h>

// MaxNormPooling2D: quaternion max-norm 2x2 pooling, stride 2, VALID.
// Inputs: x0..x3 each (B=16, H=128, W=128, C=64) fp32, NHWC.
// Output: concatenated (out0..out3), each (16, 64, 64, 64) fp32.
//
// R7: DRAM-ceiling-bound (~5.95 TB/s proven across 4 configs). Combine the
// two features that each gave best kernel time:
//   - persistent single-wave launch (no wave transitions)
//   - 256-bit ld/st.global.v8.f32 (fewest, densest memory requests)
// with EXACT work division: 256 blocks x 256 threads x 8 iterations =
// 524,288 work items. All blocks resident in one wave (2/SM), no ragged
// tail, no imbalance; 8 independent iterations/thread for cross-iteration
// MLP.

#define B_  16
#define H_  128
#define W_  128
#define C_  64
#define HO_ 64
#define WO_ 64

#define C8_ 8   // 8 groups of 8 floats per pixel channel dim
// work items = 16*64*64*8 = 524,288
#define NWORK_TOTAL (B_ * HO_ * WO_ * C8_)
// per-component output size in floats
#define OUT_COMP_F (B_ * HO_ * WO_ * C_)

#define THREADS_ 256
#define GRID_    256
#define ITERS_   (NWORK_TOTAL / (GRID_ * THREADS_))   // 8, exact

__device__ __forceinline__ void ldg_v8(const float* __restrict__ p, float* v)
{
    asm volatile("ld.global.v8.f32 {%0,%1,%2,%3,%4,%5,%6,%7}, [%8];"
                 : "=f"(v[0]), "=f"(v[1]), "=f"(v[2]), "=f"(v[3]),
                   "=f"(v[4]), "=f"(v[5]), "=f"(v[6]), "=f"(v[7])
                 : "l"(p));
}

__device__ __forceinline__ void stg_v8(float* __restrict__ p, const float* v)
{
    asm volatile("st.global.v8.f32 [%0], {%1,%2,%3,%4,%5,%6,%7,%8};"
                 :: "l"(p),
                    "f"(v[0]), "f"(v[1]), "f"(v[2]), "f"(v[3]),
                    "f"(v[4]), "f"(v[5]), "f"(v[6]), "f"(v[7])
                 : "memory");
}

__global__ __launch_bounds__(THREADS_, 2) void maxnorm_pool_kernel(
    const float* __restrict__ x0,
    const float* __restrict__ x1,
    const float* __restrict__ x2,
    const float* __restrict__ x3,
    float* __restrict__ out)
{
    const int stride = GRID_ * THREADS_;  // 65,536
    int t = blockIdx.x * THREADS_ + threadIdx.x;

#pragma unroll 1
    for (int it = 0; it < ITERS_; ++it, t += stride) {
        int c8  = t & (C8_ - 1);
        int pix = t >> 3;             // b*HO*WO + ho*WO + wo
        int wo  = pix & (WO_ - 1);
        int ho  = (pix >> 6) & (HO_ - 1);
        int b   = pix >> 12;

        int h0 = ho << 1;
        int w0 = wo << 1;

        // float-unit index of this thread's 8-channel chunk at window origin
        int base = ((b * H_ + h0) * W_ + w0) * C_ + (c8 << 3);
        // window positions in row-major order: (0,0),(0,1),(1,0),(1,1)
        int off[4];
        off[0] = base;
        off[1] = base + C_;           // dw=1
        off[2] = base + W_ * C_;      // dh=1
        off[3] = base + W_ * C_ + C_;

        // best norm per channel lane (norms >= 0; -1 => p=0 wins first,
        // first-max tie-break like TF/argmax)
        float bn[8];
        float o0[8], o1[8], o2[8], o3[8];
#pragma unroll
        for (int i = 0; i < 8; ++i) bn[i] = -1.f;

#pragma unroll
        for (int p = 0; p < 4; ++p) {
            float a0[8], a1[8], a2[8], a3[8];
            ldg_v8(x0 + off[p], a0);
            ldg_v8(x1 + off[p], a1);
            ldg_v8(x2 + off[p], a2);
            ldg_v8(x3 + off[p], a3);

#pragma unroll
            for (int i = 0; i < 8; ++i) {
                // sequential sum order x0^2 + x1^2 + x2^2 + x3^2, then sqrt —
                // matches the reference's comparison domain for tie behavior.
                float n = sqrtf(a0[i] * a0[i] + a1[i] * a1[i] +
                                a2[i] * a2[i] + a3[i] * a3[i]);
                if (n > bn[i]) {
                    bn[i] = n;
                    o0[i] = a0[i]; o1[i] = a1[i];
                    o2[i] = a2[i]; o3[i] = a3[i];
                }
            }
        }

        int obase = pix * C_ + (c8 << 3);   // within one component, floats
        stg_v8(out + obase,                  o0);
        stg_v8(out + obase +     OUT_COMP_F, o1);
        stg_v8(out + obase + 2 * OUT_COMP_F, o2);
        stg_v8(out + obase + 3 * OUT_COMP_F, o3);
    }
}

extern "C" void kernel_launch(void* const* d_in, const int* in_sizes, int n_in,
                              void* d_out, int out_size)
{
    const float* x0 = (const float*)d_in[0];
    const float* x1 = (const float*)d_in[1];
    const float* x2 = (const float*)d_in[2];
    const float* x3 = (const float*)d_in[3];
    float* out = (float*)d_out;

    maxnorm_pool_kernel<<<GRID_, THREADS_>>>(x0, x1, x2, x3, out);
}